// round 13
// baseline (speedup 1.0000x reference)
#include <cuda_runtime.h>
#include <math.h>
#include <stdint.h>

#define NATOMS 16384
#define NEDGES 262144
#define DIM    128
#define GDIM   50
#define LINT   4
#define TBL    4096
#define NMOLS  32

#define DMAXF  1.74f
#define LOG2C  0.69314718055994530942f
#define PIC    3.14159265358979323846f

// -------------------- scratch (static device globals; no runtime alloc) ----
__device__ __align__(16) float g_h[NATOMS * DIM];
__device__ __align__(16) float g_xh[NATOMS * DIM];
__device__ __align__(16) float g_agg[NATOMS * DIM];
__device__ __align__(16) float g_dist[NEDGES];
__device__ __align__(16) float g_table[(size_t)LINT * TBL * DIM];
__device__ __align__(16) float g_u[DIM];
__device__ __align__(16) float g_v[DIM];

__device__ __forceinline__ float sspf(float x) {
    return fmaxf(x, 0.0f) + log1pf(expf(-fabsf(x))) - LOG2C;
}

// -------------------- packed f32x2 helpers (FFMA2 — 2x fp32 FMA rate) ------
__device__ __forceinline__ unsigned long long pack2(float x) {
    unsigned long long r;
    asm("mov.b64 %0, {%1, %1};" : "=l"(r) : "f"(x));
    return r;
}
__device__ __forceinline__ void ffma2(unsigned long long& c,
                                      unsigned long long a,
                                      unsigned long long b) {
    asm("fma.rn.f32x2 %0, %1, %2, %3;" : "=l"(c) : "l"(a), "l"(b), "l"(c));
}
__device__ __forceinline__ float2 up2(unsigned long long v) {
    float2 f;
    asm("mov.b64 {%0, %1}, %2;" : "=f"(f.x), "=f"(f.y) : "l"(v));
    return f;
}

// -------------------- prep: u = emb_W@cf1[0], v = emb_b@cf1[0] -------------
__global__ void k_prep(const float* __restrict__ eW, const float* __restrict__ eb,
                       const float* __restrict__ cf1) {
    int f = threadIdx.x;
    float u = 0.f, v = 0.f;
    #pragma unroll 8
    for (int d = 0; d < DIM; ++d) {
        float w = __ldg(cf1 + d * DIM + f);
        u = fmaf(__ldg(eW + d), w, u);
        v = fmaf(__ldg(eb + d), w, v);
    }
    g_u[f] = u;
    g_v[f] = v;
}

// -------------------- embed: h = z*W+b; xh = z*u+v; zero agg + out ---------
__global__ void k_embed(const float* __restrict__ z,
                        const float* __restrict__ eW,
                        const float* __restrict__ eb,
                        float* __restrict__ out) {
    int idx = blockIdx.x * blockDim.x + threadIdx.x;   // float4 index
    if (blockIdx.x == 0 && threadIdx.x < NMOLS) out[threadIdx.x] = 0.0f;
    int n = idx >> 5;
    int c = (idx & 31) << 2;
    float zv = __ldg(z + n);
    float4 w = *reinterpret_cast<const float4*>(eW + c);
    float4 b = *reinterpret_cast<const float4*>(eb + c);
    float4 h;
    h.x = fmaf(zv, w.x, b.x); h.y = fmaf(zv, w.y, b.y);
    h.z = fmaf(zv, w.z, b.z); h.w = fmaf(zv, w.w, b.w);
    size_t off = (size_t)n * DIM + c;
    *reinterpret_cast<float4*>(g_h + off) = h;
    float4 u = *reinterpret_cast<const float4*>(g_u + c);
    float4 v = *reinterpret_cast<const float4*>(g_v + c);
    float4 x;
    x.x = fmaf(zv, u.x, v.x); x.y = fmaf(zv, u.y, v.y);
    x.z = fmaf(zv, u.z, v.z); x.w = fmaf(zv, u.w, v.w);
    *reinterpret_cast<float4*>(g_xh + off) = x;
    *reinterpret_cast<float4*>(g_agg + off) = make_float4(0.f, 0.f, 0.f, 0.f);
}

// -------------------- edge distances ---------------------------------------
__global__ void k_dist(const float* __restrict__ pos,
                       const int* __restrict__ src,
                       const int* __restrict__ dst) {
    int e = blockIdx.x * blockDim.x + threadIdx.x;
    int s = __ldg(src + e);
    int d = __ldg(dst + e);
    float dx = __ldg(pos + s * 3 + 0) - __ldg(pos + d * 3 + 0);
    float dy = __ldg(pos + s * 3 + 1) - __ldg(pos + d * 3 + 1);
    float dz = __ldg(pos + s * 3 + 2) - __ldg(pos + d * 3 + 2);
    g_dist[e] = sqrtf(fmaf(dx, dx, fmaf(dy, dy, fmaf(dz, dz, 1e-12f))));
}

// -------------------- filter table: Wf(d)*C(d); 2 entries in flight --------
// 512 blocks (4 layers x 128 chunks of 32), 256 threads (two 128-halves)
__global__ void k_table(const float* __restrict__ W1, const float* __restrict__ b1,
                        const float* __restrict__ W2, const float* __restrict__ b2) {
    extern __shared__ float sm[];
    float* sW1  = sm;                       // 50*128
    float* sW2  = sW1 + GDIM * DIM;         // 128*128
    float* srbf = sW2 + DIM * DIM;          // 2*64
    float* st1  = srbf + 128;               // 2*128
    int tid  = threadIdx.x;
    int half = tid >> 7;
    int tl   = tid & 127;
    int l    = blockIdx.x >> 7;
    int t0   = (blockIdx.x & 127) * 32;

    for (int i = tid; i < GDIM * DIM; i += 256) sW1[i] = W1[(size_t)l * GDIM * DIM + i];
    for (int i = tid; i < DIM * DIM; i += 256)  sW2[i] = W2[(size_t)l * DIM * DIM + i];
    float myb1 = __ldg(b1 + l * DIM + tl);
    float myb2 = __ldg(b2 + l * DIM + tl);
    __syncthreads();

    const float dstep = DMAXF / (float)(TBL - 1);
    for (int tt = 0; tt < 32; tt += 2) {
        int t = t0 + tt + half;
        float d = (float)t * dstep;
        if (tl < GDIM) {
            float mu = (float)tl * (5.0f / 49.0f);
            float u = d - mu;
            srbf[half * 64 + tl] = expf(-4.0f * u * u);
        }
        __syncthreads();
        float acc = myb1;
        const float* rb = srbf + half * 64;
        #pragma unroll 10
        for (int g = 0; g < GDIM; ++g) acc = fmaf(rb[g], sW1[g * DIM + tl], acc);
        st1[half * DIM + tl] = sspf(acc);
        __syncthreads();
        float o = myb2;
        const float* t1 = st1 + half * DIM;
        #pragma unroll 8
        for (int j = 0; j < DIM; ++j) o = fmaf(t1[j], sW2[j * DIM + tl], o);
        float C = 0.5f * (cosf(d * (PIC / 5.0f)) + 1.0f);
        g_table[((size_t)l * TBL + t) * DIM + tl] = o * C;
        __syncthreads();
    }
}

// -------------------- edge pass: gather * lerp(table) -> scatter-add -------
__global__ void k_edge(const int* __restrict__ src, const int* __restrict__ dst, int l) {
    int gt   = blockIdx.x * 256 + threadIdx.x;
    int e    = gt >> 5;
    int lane = gt & 31;
    int s  = __ldg(src + e);
    int dd = __ldg(dst + e);
    float dist = g_dist[e];
    float p = dist * ((float)(TBL - 1) / DMAXF);
    int   i = (int)p;
    i = min(i, TBL - 2);
    float w = p - (float)i;
    const float4* trow = reinterpret_cast<const float4*>(g_table + ((size_t)l * TBL + i) * DIM) + lane;
    float4 a = trow[0];
    float4 b = trow[32];
    float4 xj = reinterpret_cast<const float4*>(g_xh + (size_t)s * DIM)[lane];
    float4 v;
    v.x = xj.x * fmaf(w, b.x - a.x, a.x);
    v.y = xj.y * fmaf(w, b.y - a.y, a.y);
    v.z = xj.z * fmaf(w, b.z - a.z, a.z);
    v.w = xj.w * fmaf(w, b.w - a.w, a.w);
    float* outp = g_agg + (size_t)dd * DIM + lane * 4;
    asm volatile("red.global.add.v4.f32 [%0], {%1,%2,%3,%4};"
                 :: "l"(outp), "f"(v.x), "f"(v.y), "f"(v.z), "f"(v.w) : "memory");
}

// -------------------- FFMA2 128x128x128 tile GEMM --------------------------
// sA: [128][132] (m,k) row-major. sW: [128][128] (k,n). Thread: 4x8 (as 4x4 pairs).
__device__ __forceinline__ void mma128v(const float* __restrict__ sA,
                                        const float* __restrict__ sW,
                                        unsigned long long c2[4][4],
                                        int m0, int n0) {
    #pragma unroll 4
    for (int k = 0; k < DIM; ++k) {
        ulonglong2 B0 = *reinterpret_cast<const ulonglong2*>(sW + k * DIM + n0);
        ulonglong2 B1 = *reinterpret_cast<const ulonglong2*>(sW + k * DIM + n0 + 4);
        #pragma unroll
        for (int i = 0; i < 4; ++i) {
            unsigned long long aa = pack2(sA[(m0 + i) * 132 + k]);
            ffma2(c2[i][0], aa, B0.x);
            ffma2(c2[i][1], aa, B0.y);
            ffma2(c2[i][2], aa, B1.x);
            ffma2(c2[i][3], aa, B1.y);
        }
    }
}

__device__ __forceinline__ void zero_acc(unsigned long long c2[4][4]) {
    #pragma unroll
    for (int i = 0; i < 4; ++i)
        #pragma unroll
        for (int j = 0; j < 4; ++j) c2[i][j] = 0ull;
}

// -------------------- fused node update: 3 chained GEMMs per tile ----------
// x1 = ssp(agg@cf2 + b); x2 = x1@int + b; h += x2; xh = h@cf1_next (if any).
// Also zeroes its g_agg tile for the next layer (if any).
__global__ void __launch_bounds__(512, 1) k_node(
    const float* __restrict__ cf2W, const float* __restrict__ cf2b,
    const float* __restrict__ intW, const float* __restrict__ intb,
    const float* __restrict__ cf1Wn, int hasNext) {
    extern __shared__ float sm[];
    float* sA = sm;                 // 128*132
    float* sW = sm + 128 * 132;     // 128*128
    int tid  = threadIdx.x;
    int row0 = blockIdx.x * 128;
    int m0 = (tid >> 4) * 4, n0 = (tid & 15) * 8;

    // stage: A = agg tile, W = cf2
    #pragma unroll
    for (int it = 0; it < 8; ++it) {
        int idx = tid + it * 512;          // float4 index 0..4095
        int m = idx >> 5, c4 = (idx & 31) << 2;
        *reinterpret_cast<float4*>(sA + m * 132 + c4) =
            *reinterpret_cast<const float4*>(g_agg + (size_t)(row0 + m) * DIM + c4);
        *reinterpret_cast<float4*>(sW + idx * 4) =
            *reinterpret_cast<const float4*>(cf2W + (size_t)idx * 4);
    }
    __syncthreads();
    // zero our agg tile for the next layer's scatter (overlaps mma)
    if (hasNext) {
        #pragma unroll
        for (int it = 0; it < 8; ++it) {
            int idx = tid + it * 512;
            int m = idx >> 5, c4 = (idx & 31) << 2;
            *reinterpret_cast<float4*>(g_agg + (size_t)(row0 + m) * DIM + c4) =
                make_float4(0.f, 0.f, 0.f, 0.f);
        }
    }

    unsigned long long c2[4][4];
    zero_acc(c2);
    mma128v(sA, sW, c2, m0, n0);
    __syncthreads();   // done reading sA/sW

    // x1 = ssp(c + cf2b) -> sA; load int weights
    {
        float bb[8];
        #pragma unroll
        for (int j = 0; j < 8; ++j) bb[j] = __ldg(cf2b + n0 + j);
        #pragma unroll
        for (int i = 0; i < 4; ++i) {
            float2 p0 = up2(c2[i][0]), p1 = up2(c2[i][1]);
            float2 p2 = up2(c2[i][2]), p3 = up2(c2[i][3]);
            float4 o0 = make_float4(sspf(p0.x + bb[0]), sspf(p0.y + bb[1]),
                                    sspf(p1.x + bb[2]), sspf(p1.y + bb[3]));
            float4 o1 = make_float4(sspf(p2.x + bb[4]), sspf(p2.y + bb[5]),
                                    sspf(p3.x + bb[6]), sspf(p3.y + bb[7]));
            float* p = sA + (m0 + i) * 132 + n0;
            *reinterpret_cast<float4*>(p)     = o0;
            *reinterpret_cast<float4*>(p + 4) = o1;
        }
    }
    #pragma unroll
    for (int it = 0; it < 8; ++it) {
        int idx = tid + it * 512;
        *reinterpret_cast<float4*>(sW + idx * 4) =
            *reinterpret_cast<const float4*>(intW + (size_t)idx * 4);
    }
    __syncthreads();
    zero_acc(c2);
    mma128v(sA, sW, c2, m0, n0);
    __syncthreads();

    // hnew = h + c + intb -> global (+ stage into sA if next GEMM)
    {
        float bb[8];
        #pragma unroll
        for (int j = 0; j < 8; ++j) bb[j] = __ldg(intb + n0 + j);
        #pragma unroll
        for (int i = 0; i < 4; ++i) {
            size_t off = (size_t)(row0 + m0 + i) * DIM + n0;
            float4 h0 = *reinterpret_cast<const float4*>(g_h + off);
            float4 h1 = *reinterpret_cast<const float4*>(g_h + off + 4);
            float2 p0 = up2(c2[i][0]), p1 = up2(c2[i][1]);
            float2 p2 = up2(c2[i][2]), p3 = up2(c2[i][3]);
            h0.x += p0.x + bb[0]; h0.y += p0.y + bb[1];
            h0.z += p1.x + bb[2]; h0.w += p1.y + bb[3];
            h1.x += p2.x + bb[4]; h1.y += p2.y + bb[5];
            h1.z += p3.x + bb[6]; h1.w += p3.y + bb[7];
            *reinterpret_cast<float4*>(g_h + off)     = h0;
            *reinterpret_cast<float4*>(g_h + off + 4) = h1;
            if (hasNext) {
                float* p = sA + (m0 + i) * 132 + n0;
                *reinterpret_cast<float4*>(p)     = h0;
                *reinterpret_cast<float4*>(p + 4) = h1;
            }
        }
    }
    if (!hasNext) return;

    #pragma unroll
    for (int it = 0; it < 8; ++it) {
        int idx = tid + it * 512;
        *reinterpret_cast<float4*>(sW + idx * 4) =
            *reinterpret_cast<const float4*>(cf1Wn + (size_t)idx * 4);
    }
    __syncthreads();
    zero_acc(c2);
    mma128v(sA, sW, c2, m0, n0);
    #pragma unroll
    for (int i = 0; i < 4; ++i) {
        size_t off = (size_t)(row0 + m0 + i) * DIM + n0;
        float2 p0 = up2(c2[i][0]), p1 = up2(c2[i][1]);
        float2 p2 = up2(c2[i][2]), p3 = up2(c2[i][3]);
        *reinterpret_cast<float4*>(g_xh + off)     = make_float4(p0.x, p0.y, p1.x, p1.y);
        *reinterpret_cast<float4*>(g_xh + off + 4) = make_float4(p2.x, p2.y, p3.x, p3.y);
    }
}

// -------------------- readout: ssp(h@lin1+b)@lin2+b, segment-sum by batch --
__global__ void k_readout(const int* __restrict__ batch,
                          const float* __restrict__ l1W, const float* __restrict__ l1b,
                          const float* __restrict__ l2W, const float* __restrict__ l2b,
                          float* __restrict__ out) {
    __shared__ float sW1[DIM * 64];
    __shared__ float sW2[64];
    __shared__ float sh[8 * DIM];
    int tid = threadIdx.x, lane = tid & 31, wid = tid >> 5;
    for (int i = tid; i < DIM * 64; i += 256) sW1[i] = l1W[i];
    if (tid < 64) sW2[tid] = l2W[tid];
    int n = blockIdx.x * 8 + wid;
    float4 hv = reinterpret_cast<const float4*>(g_h + (size_t)n * DIM)[lane];
    *reinterpret_cast<float4*>(sh + wid * DIM + lane * 4) = hv;
    __syncthreads();
    float t0 = __ldg(l1b + lane), t1 = __ldg(l1b + lane + 32);
    const float* hr = sh + wid * DIM;
    #pragma unroll 8
    for (int j = 0; j < DIM; ++j) {
        float hj = hr[j];
        t0 = fmaf(hj, sW1[j * 64 + lane], t0);
        t1 = fmaf(hj, sW1[j * 64 + lane + 32], t1);
    }
    float y = sspf(t0) * sW2[lane] + sspf(t1) * sW2[lane + 32];
    #pragma unroll
    for (int o = 16; o; o >>= 1) y += __shfl_xor_sync(0xffffffffu, y, o);
    if (lane == 0) atomicAdd(out + __ldg(batch + n), y + __ldg(l2b));
}

// -------------------- launch -----------------------------------------------
extern "C" void kernel_launch(void* const* d_in, const int* in_sizes, int n_in,
                              void* d_out, int out_size) {
    const float* z    = (const float*)d_in[0];
    const float* pos  = (const float*)d_in[1];
    const int*   batc = (const int*)  d_in[2];
    const int*   esrc = (const int*)  d_in[3];
    const int*   edst = (const int*)  d_in[4];
    const float* embW = (const float*)d_in[5];
    const float* embB = (const float*)d_in[6];
    const float* W1   = (const float*)d_in[7];
    const float* b1   = (const float*)d_in[8];
    const float* W2   = (const float*)d_in[9];
    const float* b2   = (const float*)d_in[10];
    const float* cf1  = (const float*)d_in[11];
    const float* cf2  = (const float*)d_in[12];
    const float* cf2b = (const float*)d_in[13];
    const float* ilW  = (const float*)d_in[14];
    const float* ilb  = (const float*)d_in[15];
    const float* l1W  = (const float*)d_in[16];
    const float* l1b  = (const float*)d_in[17];
    const float* l2W  = (const float*)d_in[18];
    const float* l2b  = (const float*)d_in[19];
    float* out = (float*)d_out;

    int smemNode = (128 * 132 + 128 * 128) * 4;                 // 133120 B
    int smemTbl  = (GDIM * DIM + DIM * DIM + 128 + 2 * DIM) * 4; // 92672 B
    cudaFuncSetAttribute(k_node,  cudaFuncAttributeMaxDynamicSharedMemorySize, smemNode);
    cudaFuncSetAttribute(k_table, cudaFuncAttributeMaxDynamicSharedMemorySize, smemTbl);

    k_prep<<<1, DIM>>>(embW, embB, cf1);
    k_embed<<<(NATOMS * DIM / 4) / 256, 256>>>(z, embW, embB, out);
    k_dist<<<NEDGES / 256, 256>>>(pos, esrc, edst);
    k_table<<<LINT * (TBL / 32), 256, smemTbl>>>(W1, b1, W2, b2);

    for (int l = 0; l < LINT; ++l) {
        k_edge<<<NEDGES / 8, 256>>>(esrc, edst, l);
        const float* cf1n = (l + 1 < LINT) ? (cf1 + (size_t)(l + 1) * DIM * DIM) : cf1;
        k_node<<<NATOMS / 128, 512, smemNode>>>(
            cf2 + (size_t)l * DIM * DIM, cf2b + l * DIM,
            ilW + (size_t)l * DIM * DIM, ilb + l * DIM,
            cf1n, (l + 1 < LINT) ? 1 : 0);
    }
    k_readout<<<NATOMS / 8, 256>>>(batc, l1W, l1b, l2W, l2b, out);
}

// round 14
// speedup vs baseline: 1.6803x; 1.6803x over previous
#include <cuda_runtime.h>
#include <math.h>
#include <stdint.h>

#define NATOMS 16384
#define NEDGES 262144
#define DIM    128
#define GDIM   50
#define LINT   4
#define TBL    4096
#define NMOLS  32

#define DMAXF  1.74f
#define LOG2C  0.69314718055994530942f
#define PIC    3.14159265358979323846f

// -------------------- scratch (static device globals; no runtime alloc) ----
__device__ __align__(16) float g_h[NATOMS * DIM];
__device__ __align__(16) float g_xh[NATOMS * DIM];
__device__ __align__(16) float g_agg[NATOMS * DIM];
__device__ __align__(16) float g_dist[NEDGES];
__device__ __align__(16) float g_table[(size_t)LINT * TBL * DIM];
__device__ __align__(16) float g_u[DIM];
__device__ __align__(16) float g_v[DIM];

__device__ __forceinline__ float sspf(float x) {
    return fmaxf(x, 0.0f) + log1pf(expf(-fabsf(x))) - LOG2C;
}

// -------------------- prep: u = emb_W@cf1[0], v = emb_b@cf1[0] -------------
__global__ void k_prep(const float* __restrict__ eW, const float* __restrict__ eb,
                       const float* __restrict__ cf1) {
    int f = threadIdx.x;
    float u = 0.f, v = 0.f;
    #pragma unroll 8
    for (int d = 0; d < DIM; ++d) {
        float w = __ldg(cf1 + d * DIM + f);
        u = fmaf(__ldg(eW + d), w, u);
        v = fmaf(__ldg(eb + d), w, v);
    }
    g_u[f] = u;
    g_v[f] = v;
}

// -------------------- embed: h = z*W+b; xh = z*u+v; zero agg + out ---------
__global__ void k_embed(const float* __restrict__ z,
                        const float* __restrict__ eW,
                        const float* __restrict__ eb,
                        float* __restrict__ out) {
    int idx = blockIdx.x * blockDim.x + threadIdx.x;   // float4 index
    if (blockIdx.x == 0 && threadIdx.x < NMOLS) out[threadIdx.x] = 0.0f;
    int n = idx >> 5;
    int c = (idx & 31) << 2;
    float zv = __ldg(z + n);
    float4 w = *reinterpret_cast<const float4*>(eW + c);
    float4 b = *reinterpret_cast<const float4*>(eb + c);
    float4 h;
    h.x = fmaf(zv, w.x, b.x); h.y = fmaf(zv, w.y, b.y);
    h.z = fmaf(zv, w.z, b.z); h.w = fmaf(zv, w.w, b.w);
    size_t off = (size_t)n * DIM + c;
    *reinterpret_cast<float4*>(g_h + off) = h;
    float4 u = *reinterpret_cast<const float4*>(g_u + c);
    float4 v = *reinterpret_cast<const float4*>(g_v + c);
    float4 x;
    x.x = fmaf(zv, u.x, v.x); x.y = fmaf(zv, u.y, v.y);
    x.z = fmaf(zv, u.z, v.z); x.w = fmaf(zv, u.w, v.w);
    *reinterpret_cast<float4*>(g_xh + off) = x;
    *reinterpret_cast<float4*>(g_agg + off) = make_float4(0.f, 0.f, 0.f, 0.f);
}

// -------------------- edge distances ---------------------------------------
__global__ void k_dist(const float* __restrict__ pos,
                       const int* __restrict__ src,
                       const int* __restrict__ dst) {
    int e = blockIdx.x * blockDim.x + threadIdx.x;
    int s = __ldg(src + e);
    int d = __ldg(dst + e);
    float dx = __ldg(pos + s * 3 + 0) - __ldg(pos + d * 3 + 0);
    float dy = __ldg(pos + s * 3 + 1) - __ldg(pos + d * 3 + 1);
    float dz = __ldg(pos + s * 3 + 2) - __ldg(pos + d * 3 + 2);
    g_dist[e] = sqrtf(fmaf(dx, dx, fmaf(dy, dy, fmaf(dz, dz, 1e-12f))));
}

// -------------------- table build as two chained GEMMs ---------------------
// out[l,t,f] = (ssp(rbf[t,:]@W1[l] + b1[l]) @ W2[l] + b2[l]) * C(t)
// grid = LINT * (TBL/128) = 128 blocks, 256 threads, 8x8 register tiles.
__global__ void __launch_bounds__(256, 1) k_table(
    const float* __restrict__ W1, const float* __restrict__ b1,
    const float* __restrict__ W2, const float* __restrict__ b2) {
    extern __shared__ float sm[];
    float* sX = sm;                  // 128*132  (x1 after GEMM1)
    float* sW = sm + 128 * 132;      // 128*128  (W1 first 50 rows, then W2)
    float* sR = sW + DIM * DIM;      // 128*52   (rbf tile)
    int tid = threadIdx.x;
    int l   = blockIdx.x >> 5;
    int t0  = (blockIdx.x & 31) * 128;
    const float dstep = DMAXF / (float)(TBL - 1);

    // stage W1 [50][128]
    for (int i = tid; i < GDIM * DIM; i += 256)
        sW[i] = W1[(size_t)l * GDIM * DIM + i];
    // rbf tile [128][50] (stride 52)
    for (int idx = tid; idx < 128 * GDIM; idx += 256) {
        int m = idx / GDIM, g = idx - m * GDIM;
        float d = (float)(t0 + m) * dstep;
        float u = d - (float)g * (5.0f / 49.0f);
        sR[m * 52 + g] = expf(-4.0f * u * u);
    }
    __syncthreads();

    int m0 = (tid >> 4) * 8, n0 = (tid & 15) * 8;
    float c[8][8];
    #pragma unroll
    for (int i = 0; i < 8; ++i)
        #pragma unroll
        for (int j = 0; j < 8; ++j) c[i][j] = 0.f;

    // GEMM1: [128x50] @ [50x128]
    #pragma unroll 2
    for (int k = 0; k < GDIM; ++k) {
        float4 b0 = *reinterpret_cast<const float4*>(sW + k * DIM + n0);
        float4 b1v = *reinterpret_cast<const float4*>(sW + k * DIM + n0 + 4);
        float bb[8] = {b0.x, b0.y, b0.z, b0.w, b1v.x, b1v.y, b1v.z, b1v.w};
        #pragma unroll
        for (int i = 0; i < 8; ++i) {
            float a = sR[(m0 + i) * 52 + k];
            #pragma unroll
            for (int j = 0; j < 8; ++j) c[i][j] = fmaf(a, bb[j], c[i][j]);
        }
    }
    __syncthreads();   // done reading sW(W1); sR no longer needed

    // x1 = ssp(c + b1) -> sX; stage W2
    {
        float bb[8];
        #pragma unroll
        for (int j = 0; j < 8; ++j) bb[j] = __ldg(b1 + l * DIM + n0 + j);
        #pragma unroll
        for (int i = 0; i < 8; ++i)
            #pragma unroll
            for (int j = 0; j < 8; ++j)
                sX[(m0 + i) * 132 + n0 + j] = sspf(c[i][j] + bb[j]);
    }
    for (int idx = tid; idx < DIM * DIM / 4; idx += 256)
        *reinterpret_cast<float4*>(sW + idx * 4) =
            *reinterpret_cast<const float4*>(W2 + (size_t)l * DIM * DIM + idx * 4);
    __syncthreads();

    #pragma unroll
    for (int i = 0; i < 8; ++i)
        #pragma unroll
        for (int j = 0; j < 8; ++j) c[i][j] = 0.f;
    // GEMM2: [128x128] @ [128x128]
    #pragma unroll 2
    for (int k = 0; k < DIM; ++k) {
        float4 b0 = *reinterpret_cast<const float4*>(sW + k * DIM + n0);
        float4 b1v = *reinterpret_cast<const float4*>(sW + k * DIM + n0 + 4);
        float bb[8] = {b0.x, b0.y, b0.z, b0.w, b1v.x, b1v.y, b1v.z, b1v.w};
        #pragma unroll
        for (int i = 0; i < 8; ++i) {
            float a = sX[(m0 + i) * 132 + k];
            #pragma unroll
            for (int j = 0; j < 8; ++j) c[i][j] = fmaf(a, bb[j], c[i][j]);
        }
    }

    // store: (c + b2) * C(d)
    {
        float bb[8];
        #pragma unroll
        for (int j = 0; j < 8; ++j) bb[j] = __ldg(b2 + l * DIM + n0 + j);
        #pragma unroll
        for (int i = 0; i < 8; ++i) {
            int row = m0 + i;
            float d = (float)(t0 + row) * dstep;
            float C = 0.5f * (cosf(d * (PIC / 5.0f)) + 1.0f);
            size_t off = ((size_t)l * TBL + t0 + row) * DIM + n0;
            *reinterpret_cast<float4*>(g_table + off) = make_float4(
                (c[i][0] + bb[0]) * C, (c[i][1] + bb[1]) * C,
                (c[i][2] + bb[2]) * C, (c[i][3] + bb[3]) * C);
            *reinterpret_cast<float4*>(g_table + off + 4) = make_float4(
                (c[i][4] + bb[4]) * C, (c[i][5] + bb[5]) * C,
                (c[i][6] + bb[6]) * C, (c[i][7] + bb[7]) * C);
        }
    }
}

// -------------------- edge pass: gather * lerp(table) -> scatter-add -------
__global__ void k_edge(const int* __restrict__ src, const int* __restrict__ dst, int l) {
    int gt   = blockIdx.x * 256 + threadIdx.x;
    int e    = gt >> 5;
    int lane = gt & 31;
    int s  = __ldg(src + e);
    int dd = __ldg(dst + e);
    float dist = g_dist[e];
    float p = dist * ((float)(TBL - 1) / DMAXF);
    int   i = (int)p;
    i = min(i, TBL - 2);
    float w = p - (float)i;
    const float4* trow = reinterpret_cast<const float4*>(g_table + ((size_t)l * TBL + i) * DIM) + lane;
    float4 a = trow[0];
    float4 b = trow[32];
    float4 xj = reinterpret_cast<const float4*>(g_xh + (size_t)s * DIM)[lane];
    float4 v;
    v.x = xj.x * fmaf(w, b.x - a.x, a.x);
    v.y = xj.y * fmaf(w, b.y - a.y, a.y);
    v.z = xj.z * fmaf(w, b.z - a.z, a.z);
    v.w = xj.w * fmaf(w, b.w - a.w, a.w);
    float* outp = g_agg + (size_t)dd * DIM + lane * 4;
    asm volatile("red.global.add.v4.f32 [%0], {%1,%2,%3,%4};"
                 :: "l"(outp), "f"(v.x), "f"(v.y), "f"(v.z), "f"(v.w) : "memory");
}

// -------------------- shared-memory 128x128x128 GEMM micro-kernel ----------
// sA: [128][132] row-major A tile, sW: [128][128] row-major weights (k,n)
__device__ __forceinline__ void mma128(const float* __restrict__ sA,
                                       const float* __restrict__ sW,
                                       float c[8][8], int m0, int n0) {
    #pragma unroll 2
    for (int k = 0; k < DIM; ++k) {
        float4 b0 = *reinterpret_cast<const float4*>(sW + k * DIM + n0);
        float4 b1 = *reinterpret_cast<const float4*>(sW + k * DIM + n0 + 4);
        float bb[8] = {b0.x, b0.y, b0.z, b0.w, b1.x, b1.y, b1.z, b1.w};
        #pragma unroll
        for (int i = 0; i < 8; ++i) {
            float a = sA[(m0 + i) * 132 + k];
            #pragma unroll
            for (int j = 0; j < 8; ++j) c[i][j] = fmaf(a, bb[j], c[i][j]);
        }
    }
}

// -------------------- fused node update: 3 chained GEMMs per tile ----------
// x1 = ssp(agg@cf2 + b); x2 = x1@int + b; h += x2; xh = h@cf1_next (if any).
// Also zeroes its g_agg tile for the next layer's scatter.
__global__ void __launch_bounds__(256, 1) k_node(
    const float* __restrict__ cf2W, const float* __restrict__ cf2b,
    const float* __restrict__ intW, const float* __restrict__ intb,
    const float* __restrict__ cf1Wn, int hasNext) {
    extern __shared__ float sm[];
    float* sA = sm;                 // 128*132
    float* sW = sm + 128 * 132;     // 128*128
    int tid  = threadIdx.x;
    int row0 = blockIdx.x * 128;
    int m0 = (tid >> 4) * 8, n0 = (tid & 15) * 8;

    // stage A inputs: A = agg tile, W = cf2
    #pragma unroll
    for (int it = 0; it < 16; ++it) {
        int idx = tid + it * 256;          // float4 index 0..4095
        int m = idx >> 5, c4 = (idx & 31) * 4;
        *reinterpret_cast<float4*>(sA + m * 132 + c4) =
            *reinterpret_cast<const float4*>(g_agg + (size_t)(row0 + m) * DIM + c4);
        *reinterpret_cast<float4*>(sW + idx * 4) =
            *reinterpret_cast<const float4*>(cf2W + (size_t)idx * 4);
    }
    __syncthreads();
    // zero our agg tile for the next layer (overlaps with MMA below)
    if (hasNext) {
        #pragma unroll
        for (int it = 0; it < 16; ++it) {
            int idx = tid + it * 256;
            int m = idx >> 5, c4 = (idx & 31) * 4;
            *reinterpret_cast<float4*>(g_agg + (size_t)(row0 + m) * DIM + c4) =
                make_float4(0.f, 0.f, 0.f, 0.f);
        }
    }
    float c[8][8];
    #pragma unroll
    for (int i = 0; i < 8; ++i)
        #pragma unroll
        for (int j = 0; j < 8; ++j) c[i][j] = 0.f;
    mma128(sA, sW, c, m0, n0);
    __syncthreads();   // everyone done reading sA before overwrite

    // x1 = ssp(c + cf2b) into sA; load int weights
    {
        float bb[8];
        #pragma unroll
        for (int j = 0; j < 8; ++j) bb[j] = __ldg(cf2b + n0 + j);
        #pragma unroll
        for (int i = 0; i < 8; ++i)
            #pragma unroll
            for (int j = 0; j < 8; ++j)
                sA[(m0 + i) * 132 + n0 + j] = sspf(c[i][j] + bb[j]);
    }
    #pragma unroll
    for (int it = 0; it < 16; ++it) {
        int idx = tid + it * 256;
        *reinterpret_cast<float4*>(sW + idx * 4) =
            *reinterpret_cast<const float4*>(intW + (size_t)idx * 4);
    }
    __syncthreads();
    #pragma unroll
    for (int i = 0; i < 8; ++i)
        #pragma unroll
        for (int j = 0; j < 8; ++j) c[i][j] = 0.f;
    mma128(sA, sW, c, m0, n0);
    __syncthreads();

    // hnew = h + c + intb -> global (+ stage into sA if next GEMM)
    {
        float bb[8];
        #pragma unroll
        for (int j = 0; j < 8; ++j) bb[j] = __ldg(intb + n0 + j);
        #pragma unroll
        for (int i = 0; i < 8; ++i) {
            size_t off = (size_t)(row0 + m0 + i) * DIM + n0;
            float4 h0 = *reinterpret_cast<const float4*>(g_h + off);
            float4 h1 = *reinterpret_cast<const float4*>(g_h + off + 4);
            h0.x += c[i][0] + bb[0];
            h0.y += c[i][1] + bb[1];
            h0.z += c[i][2] + bb[2];
            h0.w += c[i][3] + bb[3];
            h1.x += c[i][4] + bb[4];
            h1.y += c[i][5] + bb[5];
            h1.z += c[i][6] + bb[6];
            h1.w += c[i][7] + bb[7];
            *reinterpret_cast<float4*>(g_h + off)     = h0;
            *reinterpret_cast<float4*>(g_h + off + 4) = h1;
            if (hasNext) {
                float* p = sA + (m0 + i) * 132 + n0;
                *reinterpret_cast<float4*>(p)     = h0;
                *reinterpret_cast<float4*>(p + 4) = h1;
            }
        }
    }
    if (!hasNext) return;

    #pragma unroll
    for (int it = 0; it < 16; ++it) {
        int idx = tid + it * 256;
        *reinterpret_cast<float4*>(sW + idx * 4) =
            *reinterpret_cast<const float4*>(cf1Wn + (size_t)idx * 4);
    }
    __syncthreads();
    #pragma unroll
    for (int i = 0; i < 8; ++i)
        #pragma unroll
        for (int j = 0; j < 8; ++j) c[i][j] = 0.f;
    mma128(sA, sW, c, m0, n0);
    #pragma unroll
    for (int i = 0; i < 8; ++i) {
        size_t off = (size_t)(row0 + m0 + i) * DIM + n0;
        *reinterpret_cast<float4*>(g_xh + off)     = make_float4(c[i][0], c[i][1], c[i][2], c[i][3]);
        *reinterpret_cast<float4*>(g_xh + off + 4) = make_float4(c[i][4], c[i][5], c[i][6], c[i][7]);
    }
}

// -------------------- readout: ssp(h@lin1+b)@lin2+b, segment-sum by batch --
__global__ void k_readout(const int* __restrict__ batch,
                          const float* __restrict__ l1W, const float* __restrict__ l1b,
                          const float* __restrict__ l2W, const float* __restrict__ l2b,
                          float* __restrict__ out) {
    __shared__ float sW1[DIM * 64];
    __shared__ float sW2[64];
    __shared__ float sh[8 * DIM];
    int tid = threadIdx.x, lane = tid & 31, wid = tid >> 5;
    for (int i = tid; i < DIM * 64; i += 256) sW1[i] = l1W[i];
    if (tid < 64) sW2[tid] = l2W[tid];
    int n = blockIdx.x * 8 + wid;
    float4 hv = reinterpret_cast<const float4*>(g_h + (size_t)n * DIM)[lane];
    *reinterpret_cast<float4*>(sh + wid * DIM + lane * 4) = hv;
    __syncthreads();
    float t0 = __ldg(l1b + lane), t1 = __ldg(l1b + lane + 32);
    const float* hr = sh + wid * DIM;
    #pragma unroll 8
    for (int j = 0; j < DIM; ++j) {
        float hj = hr[j];
        t0 = fmaf(hj, sW1[j * 64 + lane], t0);
        t1 = fmaf(hj, sW1[j * 64 + lane + 32], t1);
    }
    float y = sspf(t0) * sW2[lane] + sspf(t1) * sW2[lane + 32];
    #pragma unroll
    for (int o = 16; o; o >>= 1) y += __shfl_xor_sync(0xffffffffu, y, o);
    if (lane == 0) atomicAdd(out + __ldg(batch + n), y + __ldg(l2b));
}

// -------------------- launch -----------------------------------------------
extern "C" void kernel_launch(void* const* d_in, const int* in_sizes, int n_in,
                              void* d_out, int out_size) {
    const float* z    = (const float*)d_in[0];
    const float* pos  = (const float*)d_in[1];
    const int*   batc = (const int*)  d_in[2];
    const int*   esrc = (const int*)  d_in[3];
    const int*   edst = (const int*)  d_in[4];
    const float* embW = (const float*)d_in[5];
    const float* embB = (const float*)d_in[6];
    const float* W1   = (const float*)d_in[7];
    const float* b1   = (const float*)d_in[8];
    const float* W2   = (const float*)d_in[9];
    const float* b2   = (const float*)d_in[10];
    const float* cf1  = (const float*)d_in[11];
    const float* cf2  = (const float*)d_in[12];
    const float* cf2b = (const float*)d_in[13];
    const float* ilW  = (const float*)d_in[14];
    const float* ilb  = (const float*)d_in[15];
    const float* l1W  = (const float*)d_in[16];
    const float* l1b  = (const float*)d_in[17];
    const float* l2W  = (const float*)d_in[18];
    const float* l2b  = (const float*)d_in[19];
    float* out = (float*)d_out;

    int smemNode = (128 * 132 + 128 * 128) * 4;              // 133120 B
    int smemTbl  = (128 * 132 + 128 * 128 + 128 * 52) * 4;   // 159744 B
    cudaFuncSetAttribute(k_node,  cudaFuncAttributeMaxDynamicSharedMemorySize, smemNode);
    cudaFuncSetAttribute(k_table, cudaFuncAttributeMaxDynamicSharedMemorySize, smemTbl);

    k_prep<<<1, DIM>>>(embW, embB, cf1);
    k_embed<<<(NATOMS * DIM / 4) / 256, 256>>>(z, embW, embB, out);
    k_dist<<<NEDGES / 256, 256>>>(pos, esrc, edst);
    k_table<<<LINT * (TBL / 128), 256, smemTbl>>>(W1, b1, W2, b2);

    for (int l = 0; l < LINT; ++l) {
        k_edge<<<NEDGES / 8, 256>>>(esrc, edst, l);
        const float* cf1n = (l + 1 < LINT) ? (cf1 + (size_t)(l + 1) * DIM * DIM) : cf1;
        k_node<<<NATOMS / 128, 256, smemNode>>>(
            cf2 + (size_t)l * DIM * DIM, cf2b + l * DIM,
            ilW + (size_t)l * DIM * DIM, ilb + l * DIM,
            cf1n, (l + 1 < LINT) ? 1 : 0);
    }
    k_readout<<<NATOMS / 8, 256>>>(batc, l1W, l1b, l2W, l2b, out);
}